// round 16
// baseline (speedup 1.0000x reference)
#include <cuda_runtime.h>
#include <cuda_fp16.h>
#include <mma.h>
#include <math.h>

using namespace nvcuda;

// Problem constants
#define B_  4
#define S_  2048
#define E_  1024
#define H_  16
#define DH_ 64
#define M_  (B_ * S_)
#define OUT_ELEMS ((size_t)B_ * S_ * E_)

// Padded smem strides (halfs): break ldmatrix bank conflicts.
#define LDA 72    // 64-col tiles (144B rows)
#define LDP 40    // 32-col tiles (80B rows)

// ---------------- scratch: pre-split hi/lo fp16 (device globals) ----------
__device__ __half g_qh[M_ * E_], g_ql[M_ * E_];
__device__ __half g_kh[M_ * E_], g_kl[M_ * E_];
__device__ __half g_vh[M_ * E_], g_vl[M_ * E_];
__device__ __half g_Qh[M_ * E_], g_Ql[M_ * E_];
__device__ __half g_Kh[M_ * E_], g_Kl[M_ * E_];
__device__ __half g_Vh[M_ * E_], g_Vl[M_ * E_];
__device__ __half g_Oh[M_ * E_], g_Ol[M_ * E_];
__device__ __half g_wqh[E_ * E_], g_wql[E_ * E_];
__device__ __half g_wkh[E_ * E_], g_wkl[E_ * E_];
__device__ __half g_wvh[E_ * E_], g_wvl[E_ * E_];
__device__ __half g_woh[E_ * E_], g_wol[E_ * E_];

typedef wmma::fragment<wmma::matrix_a, 16, 16, 16, __half, wmma::row_major> HA;
typedef wmma::fragment<wmma::matrix_b, 16, 16, 16, __half, wmma::col_major> HBc;
typedef wmma::fragment<wmma::matrix_b, 16, 16, 16, __half, wmma::row_major> HBr;
typedef wmma::fragment<wmma::accumulator, 16, 16, 16, float> HC;

// ---------------------------------------------------------------------------
// Pre-split: fp32 -> (hi fp16, lo fp16), 4 elems/thread.
// ---------------------------------------------------------------------------
__global__ void split_kernel(const float* __restrict__ src,
                             __half* __restrict__ h, __half* __restrict__ l,
                             int n4)
{
    int i = blockIdx.x * blockDim.x + threadIdx.x;
    if (i >= n4) return;
    float4 v = ((const float4*)src)[i];
    __half h0 = __float2half_rn(v.x), h1 = __float2half_rn(v.y);
    __half h2 = __float2half_rn(v.z), h3 = __float2half_rn(v.w);
    __half2* H = (__half2*)(h + i * 4);
    __half2* L = (__half2*)(l + i * 4);
    H[0] = __halves2half2(h0, h1);
    H[1] = __halves2half2(h2, h3);
    L[0] = __halves2half2(__float2half_rn(v.x - __half2float(h0)),
                          __float2half_rn(v.y - __half2float(h1)));
    L[1] = __halves2half2(__float2half_rn(v.z - __half2float(h2)),
                          __float2half_rn(v.w - __half2float(h3)));
}

// split fp32 x4 -> hi/lo fp16 packed stores into smem (o even)
__device__ __forceinline__ void split_store4(
    float4 v, __half* h, __half* l, int o)
{
    __half h0 = __float2half_rn(v.x), h1 = __float2half_rn(v.y);
    __half h2 = __float2half_rn(v.z), h3 = __float2half_rn(v.w);
    __half2* H = (__half2*)(h + o);
    __half2* L = (__half2*)(l + o);
    H[0] = __halves2half2(h0, h1); H[1] = __halves2half2(h2, h3);
    L[0] = __halves2half2(__float2half_rn(v.x - __half2float(h0)),
                          __float2half_rn(v.y - __half2float(h1)));
    L[1] = __halves2half2(__float2half_rn(v.z - __half2float(h2)),
                          __float2half_rn(v.w - __half2float(h3)));
}

// split 8 staged floats (+bias already applied) -> halves -> 16B stores
__device__ __forceinline__ void split8_store(
    float4 s0, float4 s1, __half* __restrict__ Hp, __half* __restrict__ Lp)
{
    __align__(16) __half hs[8];
    __align__(16) __half ls[8];
    float v[8] = {s0.x, s0.y, s0.z, s0.w, s1.x, s1.y, s1.z, s1.w};
#pragma unroll
    for (int i = 0; i < 8; i++) {
        __half hh = __float2half_rn(v[i]);
        hs[i] = hh;
        ls[i] = __float2half_rn(v[i] - __half2float(hh));
    }
    *(uint4*)Hp = *(uint4*)hs;
    *(uint4*)Lp = *(uint4*)ls;
}

// ---------------------------------------------------------------------------
// NT GEMM on pre-split halves: C = A @ W^T + bias
// A: (Ah,Al) M x K halves row-major; W: (Wh,Wl) N x K halves.
// BM=BN=128, BK=64, 256 threads = 8 warps (2x4), warp tile 64x32.
// SPLIT_OUT: write (Ch,Cl) halves; else fp32 C.
// Dynamic smem: 4 * 128*LDA*2 = 73728 B.
// ---------------------------------------------------------------------------
#define GE_SMEM (4 * 128 * LDA * 2)
template<bool SPLIT_OUT>
__global__ void __launch_bounds__(256) gemm_h2(
    const __half* __restrict__ Ah_g, const __half* __restrict__ Al_g,
    const __half* __restrict__ Wh_g, const __half* __restrict__ Wl_g,
    const float* __restrict__ bias,
    float* __restrict__ C, __half* __restrict__ Ch, __half* __restrict__ Cl,
    int Kdim, int Ndim)
{
    extern __shared__ __align__(128) char sm[];
    __half* Ah = (__half*)sm;
    __half* Al = (__half*)(sm + 128 * LDA * 2);
    __half* Bh = (__half*)(sm + 2 * 128 * LDA * 2);
    __half* Bl = (__half*)(sm + 3 * 128 * LDA * 2);

    const int tid = threadIdx.x;
    const int w = tid >> 5, lane = tid & 31;
    const int m0 = blockIdx.y * 128, n0 = blockIdx.x * 128;
    const int wm = w & 1;     // rows wm*64
    const int wn = w >> 1;    // cols wn*32

    HC acc[4][2];
#pragma unroll
    for (int fm = 0; fm < 4; fm++)
#pragma unroll
        for (int fn = 0; fn < 2; fn++) wmma::fill_fragment(acc[fm][fn], 0.0f);

    const int r  = tid >> 1;
    const int cb = (tid & 1) * 32;

    for (int k0 = 0; k0 < Kdim; k0 += 64) {
#pragma unroll
        for (int i = 0; i < 4; i++) {
            int c = cb + i * 8;
            int o = r * LDA + c;
            *(uint4*)&Ah[o] = *(const uint4*)&Ah_g[(size_t)(m0 + r) * Kdim + k0 + c];
            *(uint4*)&Al[o] = *(const uint4*)&Al_g[(size_t)(m0 + r) * Kdim + k0 + c];
            *(uint4*)&Bh[o] = *(const uint4*)&Wh_g[(size_t)(n0 + r) * Kdim + k0 + c];
            *(uint4*)&Bl[o] = *(const uint4*)&Wl_g[(size_t)(n0 + r) * Kdim + k0 + c];
        }
        __syncthreads();

#pragma unroll
        for (int ks = 0; ks < 4; ks++) {
            const int kk = ks * 16;
            HA ah[4], al[4];
            HBc bh[2], bl[2];
#pragma unroll
            for (int fm = 0; fm < 4; fm++) {
                wmma::load_matrix_sync(ah[fm], &Ah[(wm * 64 + fm * 16) * LDA + kk], LDA);
                wmma::load_matrix_sync(al[fm], &Al[(wm * 64 + fm * 16) * LDA + kk], LDA);
            }
#pragma unroll
            for (int fn = 0; fn < 2; fn++) {
                wmma::load_matrix_sync(bh[fn], &Bh[(wn * 32 + fn * 16) * LDA + kk], LDA);
                wmma::load_matrix_sync(bl[fn], &Bl[(wn * 32 + fn * 16) * LDA + kk], LDA);
            }
#pragma unroll
            for (int fm = 0; fm < 4; fm++)
#pragma unroll
                for (int fn = 0; fn < 2; fn++) {
                    wmma::mma_sync(acc[fm][fn], ah[fm], bh[fn], acc[fm][fn]);
                    wmma::mma_sync(acc[fm][fn], ah[fm], bl[fn], acc[fm][fn]);
                    wmma::mma_sync(acc[fm][fn], al[fm], bh[fn], acc[fm][fn]);
                }
        }
        __syncthreads();
    }

    // Epilogue: stage through (dead) Ah smem, add bias.
    float* stage = (float*)Ah;
    float* my = stage + w * 256;
    const int er = lane >> 1;
    const int ec = (lane & 1) * 8;
#pragma unroll
    for (int fm = 0; fm < 4; fm++)
#pragma unroll
        for (int fn = 0; fn < 2; fn++) {
            wmma::store_matrix_sync(my, acc[fm][fn], 16, wmma::mem_row_major);
            __syncwarp();
            int gm = m0 + wm * 64 + fm * 16 + er;
            int gn = n0 + wn * 32 + fn * 16 + ec;
            float4 s0 = *(float4*)&my[er * 16 + ec];
            float4 s1 = *(float4*)&my[er * 16 + ec + 4];
            float4 b0 = *(const float4*)&bias[gn];
            float4 b1 = *(const float4*)&bias[gn + 4];
            s0.x += b0.x; s0.y += b0.y; s0.z += b0.z; s0.w += b0.w;
            s1.x += b1.x; s1.y += b1.y; s1.z += b1.z; s1.w += b1.w;
            if (SPLIT_OUT) {
                split8_store(s0, s1,
                             &Ch[(size_t)gm * Ndim + gn],
                             &Cl[(size_t)gm * Ndim + gn]);
            } else {
                *(float4*)&C[(size_t)gm * Ndim + gn]     = s0;
                *(float4*)&C[(size_t)gm * Ndim + gn + 4] = s1;
            }
            __syncwarp();
        }
}

// ---------------------------------------------------------------------------
// Scores: S[q,j] = 0.125 * Q_h[q,:].K_h[j,:]; inputs pre-split halves.
// 128x128 tile, causal tile skip. Smem 73728B.
// ---------------------------------------------------------------------------
__global__ void __launch_bounds__(256) scores16(
    const __half* __restrict__ Qh_g, const __half* __restrict__ Ql_g,
    const __half* __restrict__ Kh_g, const __half* __restrict__ Kl_g,
    float* __restrict__ scores)
{
    const int jt = blockIdx.x;
    const int qt = blockIdx.y;
    if (jt > qt) return;
    const int bh = blockIdx.z;
    const int b = bh >> 4;
    const int h = bh & 15;
    const int q0 = qt * 128, j0 = jt * 128;

    extern __shared__ __align__(128) char sm[];
    __half* Qh = (__half*)sm;
    __half* Ql = (__half*)(sm + 128 * LDA * 2);
    __half* Kh = (__half*)(sm + 2 * 128 * LDA * 2);
    __half* Kl = (__half*)(sm + 3 * 128 * LDA * 2);

    const int tid = threadIdx.x;
    const int w = tid >> 5;
    const int wm = w & 1, wn = w >> 1;

    const int r  = tid >> 1;
    const int cb = (tid & 1) * 32;
    {
        size_t qrow = ((size_t)b * S_ + q0 + r) * E_ + h * DH_;
        size_t krow = ((size_t)b * S_ + j0 + r) * E_ + h * DH_;
#pragma unroll
        for (int i = 0; i < 4; i++) {
            int c = cb + i * 8;
            int o = r * LDA + c;
            *(uint4*)&Qh[o] = *(const uint4*)&Qh_g[qrow + c];
            *(uint4*)&Ql[o] = *(const uint4*)&Ql_g[qrow + c];
            *(uint4*)&Kh[o] = *(const uint4*)&Kh_g[krow + c];
            *(uint4*)&Kl[o] = *(const uint4*)&Kl_g[krow + c];
        }
    }
    __syncthreads();

    HC acc[4][2];
#pragma unroll
    for (int fm = 0; fm < 4; fm++)
#pragma unroll
        for (int fn = 0; fn < 2; fn++) wmma::fill_fragment(acc[fm][fn], 0.0f);

#pragma unroll
    for (int ks = 0; ks < 4; ks++) {
        const int kk = ks * 16;
        HA ah[4], al[4];
        HBc bh2[2], bl[2];
#pragma unroll
        for (int fm = 0; fm < 4; fm++) {
            wmma::load_matrix_sync(ah[fm], &Qh[(wm * 64 + fm * 16) * LDA + kk], LDA);
            wmma::load_matrix_sync(al[fm], &Ql[(wm * 64 + fm * 16) * LDA + kk], LDA);
        }
#pragma unroll
        for (int fn = 0; fn < 2; fn++) {
            wmma::load_matrix_sync(bh2[fn], &Kh[(wn * 32 + fn * 16) * LDA + kk], LDA);
            wmma::load_matrix_sync(bl[fn],  &Kl[(wn * 32 + fn * 16) * LDA + kk], LDA);
        }
#pragma unroll
        for (int fm = 0; fm < 4; fm++)
#pragma unroll
            for (int fn = 0; fn < 2; fn++) {
                wmma::mma_sync(acc[fm][fn], ah[fm], bh2[fn], acc[fm][fn]);
                wmma::mma_sync(acc[fm][fn], ah[fm], bl[fn],  acc[fm][fn]);
                wmma::mma_sync(acc[fm][fn], al[fm], bh2[fn], acc[fm][fn]);
            }
    }

    float* base = scores + (size_t)bh * S_ * S_;
#pragma unroll
    for (int fm = 0; fm < 4; fm++)
#pragma unroll
        for (int fn = 0; fn < 2; fn++) {
#pragma unroll
            for (int e = 0; e < acc[fm][fn].num_elements; e++)
                acc[fm][fn].x[e] *= 0.125f;       // 1/sqrt(DH)
            wmma::store_matrix_sync(
                base + (size_t)(q0 + wm * 64 + fm * 16) * S_ + (j0 + wn * 32 + fn * 16),
                acc[fm][fn], S_, wmma::mem_row_major);
        }
}

// ---------------------------------------------------------------------------
// Softmax: one causal row per block. Writes zeros above diagonal.
// ---------------------------------------------------------------------------
__global__ void __launch_bounds__(256) softmax_kernel(float* __restrict__ attn)
{
    const int rowid = blockIdx.x;          // bh*S + q
    const int q = rowid & (S_ - 1);
    float* row = attn + (size_t)rowid * S_;

    const int tid = threadIdx.x;
    const int lane = tid & 31, wid = tid >> 5;
    __shared__ float red[8];
    __shared__ float bcast;

    float v[8];
    float m = -INFINITY;
#pragma unroll
    for (int t = 0; t < 8; t++) {
        int j = tid + t * 256;
        if (j <= q) { v[t] = row[j]; m = fmaxf(m, v[t]); }
    }
#pragma unroll
    for (int o = 16; o; o >>= 1) m = fmaxf(m, __shfl_xor_sync(0xffffffffu, m, o));
    if (lane == 0) red[wid] = m;
    __syncthreads();
    if (tid == 0) {
        float mm = red[0];
#pragma unroll
        for (int w = 1; w < 8; w++) mm = fmaxf(mm, red[w]);
        bcast = mm;
    }
    __syncthreads();
    m = bcast;

    float s = 0.f;
#pragma unroll
    for (int t = 0; t < 8; t++) {
        int j = tid + t * 256;
        if (j <= q) { v[t] = __expf(v[t] - m); s += v[t]; }
    }
#pragma unroll
    for (int o = 16; o; o >>= 1) s += __shfl_xor_sync(0xffffffffu, s, o);
    if (lane == 0) red[wid] = s;
    __syncthreads();
    if (tid == 0) {
        float ss = 0.f;
#pragma unroll
        for (int w = 0; w < 8; w++) ss += red[w];
        bcast = ss;
    }
    __syncthreads();
    const float inv = 1.0f / bcast;

#pragma unroll
    for (int t = 0; t < 8; t++) {
        int j = tid + t * 256;
        row[j] = (j <= q) ? v[t] * inv : 0.f;
    }
}

// ---------------------------------------------------------------------------
// PV: O_h[q,d] = sum_j P[q,j] V_h[j,d]. P split on the fly (fp32 attn),
// V pre-split halves. Output written pre-split (Oh, Ol) for the final GEMM.
// Block = 128q x 64d, BK=32, causal skip.
// ---------------------------------------------------------------------------
__global__ void __launch_bounds__(256) pv16(
    const float* __restrict__ attn,
    const __half* __restrict__ Vh_g, const __half* __restrict__ Vl_g,
    __half* __restrict__ Oh_g, __half* __restrict__ Ol_g)
{
    const int qt = blockIdx.x;
    const int bh = blockIdx.y;
    const int b = bh >> 4;
    const int h = bh & 15;
    const int q0 = qt * 128;

    __shared__ __align__(128) __half Ph[128 * LDP];
    __shared__ __align__(128) __half Pl[128 * LDP];
    __shared__ __align__(128) __half Vh[32 * LDA];
    __shared__ __align__(128) __half Vl[32 * LDA];

    const int tid = threadIdx.x;
    const int w = tid >> 5, lane = tid & 31;
    const int om = w >> 1;     // q offset om*32
    const int on = w & 1;      // d offset on*32

    HC acc[2][2];
#pragma unroll
    for (int fm = 0; fm < 2; fm++)
#pragma unroll
        for (int fn = 0; fn < 2; fn++) wmma::fill_fragment(acc[fm][fn], 0.0f);

    const float* arow = attn + (size_t)bh * S_ * S_;
    const int jmax = q0 + 128;       // P[q, j>q] == 0

    const int pr = tid >> 1;             // 0..127
    const int pc = (tid & 1) * 16;       // 0 or 16
    const int vr = tid >> 3;             // 0..31
    const int vc = (tid & 7) * 8;        // 0..56

    for (int j0 = 0; j0 < jmax; j0 += 32) {
#pragma unroll
        for (int i = 0; i < 4; i++) {
            int c = pc + i * 4;
            split_store4(*(const float4*)&arow[(size_t)(q0 + pr) * S_ + j0 + c],
                         Ph, Pl, pr * LDP + c);
        }
        {
            size_t vrow = ((size_t)b * S_ + j0 + vr) * E_ + h * DH_;
            *(uint4*)&Vh[vr * LDA + vc] = *(const uint4*)&Vh_g[vrow + vc];
            *(uint4*)&Vl[vr * LDA + vc] = *(const uint4*)&Vl_g[vrow + vc];
        }
        __syncthreads();

#pragma unroll
        for (int ks = 0; ks < 2; ks++) {
            const int kk = ks * 16;
            HA pa[2], pl2[2];
            HBr vb[2], vl2[2];
#pragma unroll
            for (int fm = 0; fm < 2; fm++) {
                wmma::load_matrix_sync(pa[fm],  &Ph[(om * 32 + fm * 16) * LDP + kk], LDP);
                wmma::load_matrix_sync(pl2[fm], &Pl[(om * 32 + fm * 16) * LDP + kk], LDP);
            }
#pragma unroll
            for (int fn = 0; fn < 2; fn++) {
                wmma::load_matrix_sync(vb[fn],  &Vh[kk * LDA + on * 32 + fn * 16], LDA);
                wmma::load_matrix_sync(vl2[fn], &Vl[kk * LDA + on * 32 + fn * 16], LDA);
            }
#pragma unroll
            for (int fm = 0; fm < 2; fm++)
#pragma unroll
                for (int fn = 0; fn < 2; fn++) {
                    wmma::mma_sync(acc[fm][fn], pa[fm],  vb[fn],  acc[fm][fn]);
                    wmma::mma_sync(acc[fm][fn], pa[fm],  vl2[fn], acc[fm][fn]);
                    wmma::mma_sync(acc[fm][fn], pl2[fm], vb[fn],  acc[fm][fn]);
                }
        }
        __syncthreads();
    }

    // Epilogue: stage fp32 via (dead) Ph smem, split-write Oh/Ol halves.
    float* stage = (float*)Ph;
    float* my = stage + w * 256;
    const int er = lane >> 1;
    const int ec = (lane & 1) * 8;
#pragma unroll
    for (int fm = 0; fm < 2; fm++)
#pragma unroll
        for (int fn = 0; fn < 2; fn++) {
            wmma::store_matrix_sync(my, acc[fm][fn], 16, wmma::mem_row_major);
            __syncwarp();
            int gm = q0 + om * 32 + fm * 16 + er;
            int gc = h * DH_ + on * 32 + fn * 16 + ec;
            float4 s0 = *(float4*)&my[er * 16 + ec];
            float4 s1 = *(float4*)&my[er * 16 + ec + 4];
            split8_store(s0, s1,
                         &Oh_g[((size_t)b * S_ + gm) * E_ + gc],
                         &Ol_g[((size_t)b * S_ + gm) * E_ + gc]);
            __syncwarp();
        }
}

// ---------------------------------------------------------------------------
// Launch
// ---------------------------------------------------------------------------
extern "C" void kernel_launch(void* const* d_in, const int* in_sizes, int n_in,
                              void* d_out, int out_size)
{
    const float* q  = (const float*)d_in[0];
    const float* k  = (const float*)d_in[1];
    const float* v  = (const float*)d_in[2];
    const float* wq = (const float*)d_in[3];
    const float* bq = (const float*)d_in[4];
    const float* wk = (const float*)d_in[5];
    const float* bk = (const float*)d_in[6];
    const float* wv = (const float*)d_in[7];
    const float* bv = (const float*)d_in[8];
    const float* wo = (const float*)d_in[9];
    const float* bo = (const float*)d_in[10];

    float* out  = (float*)d_out;
    float* attn = (float*)d_out + OUT_ELEMS;

    __half *qh, *ql, *kh, *kl, *vh, *vl;
    __half *Qh, *Ql, *Kh, *Kl, *Vh, *Vl, *Oh, *Ol;
    __half *wqh, *wql, *wkh, *wkl, *wvh, *wvl, *woh, *wol;
    cudaGetSymbolAddress((void**)&qh, g_qh);   cudaGetSymbolAddress((void**)&ql, g_ql);
    cudaGetSymbolAddress((void**)&kh, g_kh);   cudaGetSymbolAddress((void**)&kl, g_kl);
    cudaGetSymbolAddress((void**)&vh, g_vh);   cudaGetSymbolAddress((void**)&vl, g_vl);
    cudaGetSymbolAddress((void**)&Qh, g_Qh);   cudaGetSymbolAddress((void**)&Ql, g_Ql);
    cudaGetSymbolAddress((void**)&Kh, g_Kh);   cudaGetSymbolAddress((void**)&Kl, g_Kl);
    cudaGetSymbolAddress((void**)&Vh, g_Vh);   cudaGetSymbolAddress((void**)&Vl, g_Vl);
    cudaGetSymbolAddress((void**)&Oh, g_Oh);   cudaGetSymbolAddress((void**)&Ol, g_Ol);
    cudaGetSymbolAddress((void**)&wqh, g_wqh); cudaGetSymbolAddress((void**)&wql, g_wql);
    cudaGetSymbolAddress((void**)&wkh, g_wkh); cudaGetSymbolAddress((void**)&wkl, g_wkl);
    cudaGetSymbolAddress((void**)&wvh, g_wvh); cudaGetSymbolAddress((void**)&wvl, g_wvl);
    cudaGetSymbolAddress((void**)&woh, g_woh); cudaGetSymbolAddress((void**)&wol, g_wol);

    cudaFuncSetAttribute(gemm_h2<true>,  cudaFuncAttributeMaxDynamicSharedMemorySize, GE_SMEM);
    cudaFuncSetAttribute(gemm_h2<false>, cudaFuncAttributeMaxDynamicSharedMemorySize, GE_SMEM);
    cudaFuncSetAttribute(scores16, cudaFuncAttributeMaxDynamicSharedMemorySize, GE_SMEM);

    // ---- pre-split inputs + weights ----
    const int nW4 = E_ * E_ / 4, nI4 = M_ * E_ / 4;
    split_kernel<<<(nI4 + 255) / 256, 256>>>(q,  qh,  ql,  nI4);
    split_kernel<<<(nI4 + 255) / 256, 256>>>(k,  kh,  kl,  nI4);
    split_kernel<<<(nI4 + 255) / 256, 256>>>(v,  vh,  vl,  nI4);
    split_kernel<<<(nW4 + 255) / 256, 256>>>(wq, wqh, wql, nW4);
    split_kernel<<<(nW4 + 255) / 256, 256>>>(wk, wkh, wkl, nW4);
    split_kernel<<<(nW4 + 255) / 256, 256>>>(wv, wvh, wvl, nW4);
    split_kernel<<<(nW4 + 255) / 256, 256>>>(wo, woh, wol, nW4);

    // ---- projections (outputs written pre-split) ----
    dim3 gproj(E_ / 128, M_ / 128);   // (8, 64)
    gemm_h2<true><<<gproj, 256, GE_SMEM>>>(qh, ql, wqh, wql, bq, nullptr, Qh, Ql, E_, E_);
    gemm_h2<true><<<gproj, 256, GE_SMEM>>>(kh, kl, wkh, wkl, bk, nullptr, Kh, Kl, E_, E_);
    gemm_h2<true><<<gproj, 256, GE_SMEM>>>(vh, vl, wvh, wvl, bv, nullptr, Vh, Vl, E_, E_);

    // ---- attention ----
    dim3 gsc(S_ / 128, S_ / 128, B_ * H_);  // (16, 16, 64)
    scores16<<<gsc, 256, GE_SMEM>>>(Qh, Ql, Kh, Kl, attn);

    softmax_kernel<<<B_ * H_ * S_, 256>>>(attn);

    dim3 gpv(S_ / 128, B_ * H_);     // (16, 64)
    pv16<<<gpv, 256>>>(attn, Vh, Vl, Oh, Ol);

    // ---- output projection (fp32 out) ----
    gemm_h2<false><<<gproj, 256, GE_SMEM>>>(Oh, Ol, woh, wol, bo, out, nullptr, nullptr, E_, E_);
}